// round 6
// baseline (speedup 1.0000x reference)
#include <cuda_runtime.h>
#include <cstdint>

// TSBRNN: B=8192 rows, T=4096, per-row 2-state swap recurrence.
// R6 = R2 (best known) + burst refills: cp.async ring deepened to 12 tiles,
// refilled 4 consecutive tiles at a time with per-row-contiguous issue order
// (1KB per DRAM page delivered back-to-back) to fix DRAM page thrashing.

namespace {
constexpr int T_LEN   = 4096;
constexpr int TT      = 64;               // timesteps per tile
constexpr int NT      = T_LEN / TT;       // 64 tiles
constexpr int WROWS   = 32;               // rows per warp (1 row/lane)
constexpr int WARPS   = 2;
constexpr int THREADS = 32 * WARPS;       // 64
constexpr int ROWS    = WROWS * WARPS;    // 64 rows/CTA -> grid 128 (one wave)
constexpr int STAGES  = 12;               // 3 bursts of 4 tiles
constexpr int BURST   = 4;                // tiles per refill burst
constexpr int TILE_F  = WROWS * TT;       // 2048 floats = 8KB per stage
constexpr int WBUF_F  = STAGES * TILE_F;  // 96KB per warp
constexpr int SMEM_FLOATS = WARPS * WBUF_F + T_LEN;
constexpr int SMEM_BYTES  = SMEM_FLOATS * 4;   // 192KB + 16KB = 208KB
}

__device__ __forceinline__ void cp_async16(uint32_t dst, const void* src) {
    asm volatile("cp.async.cg.shared.global [%0], [%1], 16;\n" :: "r"(dst), "l"(src));
}
__device__ __forceinline__ void cp_commit() {
    asm volatile("cp.async.commit_group;\n" ::: "memory");
}
template <int N>
__device__ __forceinline__ void cp_wait() {
    asm volatile("cp.async.wait_group %0;\n" :: "n"(N) : "memory");
}

__global__ void __launch_bounds__(THREADS, 1)
tsb_kernel(const float* __restrict__ x, const float* __restrict__ alpha_p,
           const float* __restrict__ beta_p, float* __restrict__ out) {
    extern __shared__ float smem[];
    float* aX = smem + WARPS * WBUF_F;   // alpha * x[0, t]

    const int tid  = threadIdx.x;
    const int wid  = tid >> 5;
    const int lane = tid & 31;
    const float alpha  = __ldg(alpha_p);
    const float beta   = __ldg(beta_p);
    const float omb    = 1.0f - beta;
    const float nalpha = -alpha;

    // Stage the global level-driver sequence once per CTA (L2-shared across CTAs)
#pragma no_unroll
    for (int i = tid; i < T_LEN / 4; i += THREADS) {
        float4 v = __ldg(reinterpret_cast<const float4*>(x) + i);
        v.x *= alpha; v.y *= alpha; v.z *= alpha; v.w *= alpha;
        reinterpret_cast<float4*>(aX)[i] = v;
    }
    __syncthreads();   // only barrier

    const int row_base = blockIdx.x * ROWS + wid * WROWS;
    float* wbuf = smem + wid * WBUF_F;
    const uint32_t wbuf_sa = (uint32_t)__cvta_generic_to_shared(wbuf);
    const float* xbase = x + (size_t)row_base * T_LEN;

    // Burst load of 4 consecutive tiles (tb0 .. tb0+3), issue order arranged so
    // each row's 1KB (4 tiles x 256B, contiguous in T) goes out back-to-back.
    // Per instruction i: lanes cover rows 2i,2i+1 with 16 chunks of 16B each.
    auto load_burst = [&](int tb0) {
        int slot0 = tb0 % STAGES;          // burst-aligned: no wrap within burst
        int row   = (lane >> 4) ;          // used via idx math below
#pragma unroll
        for (int i = 0; i < 16; ++i) {     // row pairs
#pragma unroll
            for (int tb = 0; tb < BURST; ++tb) {
                int idx = lane + 32 * i;   // 0..511
                int r   = idx >> 4;        // 2 rows per instruction
                int j4  = idx & 15;
                int js  = j4 ^ (r & 7);    // conflict-free for compute LDS.128
                const float* src = xbase + (size_t)r * T_LEN + (tb0 + tb) * TT + j4 * 4;
                uint32_t dst = wbuf_sa +
                    (uint32_t)((slot0 + tb) * TILE_F + r * TT + js * 4) * 4u;
                cp_async16(dst, src);
            }
        }
        (void)row;
    };

    // Prologue: 2 bursts (tiles 0..7)
    load_burst(0);  cp_commit();
    load_burst(4);  cp_commit();

    float A = 0.0f, Bs = 0.0f;
    const int swz = lane & 7;
    float* og_row = out + (size_t)(row_base + lane) * T_LEN;

#define TSB_STEP(xval, aval, oval)                      \
    {                                                   \
        float nz  = fminf(fabsf(xval), 1.0f);           \
        float bnz = fminf(fabsf(xval), beta);           \
        float t1  = fmaf(nalpha, A, aval);              \
        float Bn  = fmaf(nz, t1, A);                    \
        float An  = fmaf(Bs, omb, bnz);                 \
        oval = An * Bn; A = An; Bs = Bn;                \
    }

    for (int tile = 0; tile < NT; ++tile) {
        if ((tile & (BURST - 1)) == 0) {
            int nb = tile + 2 * BURST;     // keep 2 bursts ahead
            if (nb < NT) { load_burst(nb); cp_commit(); }
            // Wait for the burst covering [tile, tile+3].
            if (tile < NT - 2 * BURST)      cp_wait<2>();
            else if (tile == NT - 2*BURST)  cp_wait<1>();
            else                            cp_wait<0>();
        }

        const float* xr  = wbuf + (tile % STAGES) * TILE_F + lane * TT;
        const float* aXt = aX + tile * TT;
        float* og = og_row + tile * TT;

#pragma unroll
        for (int j8 = 0; j8 < TT / 8; ++j8) {
            int j4a = (2 * j8) ^ swz;
            int j4b = j4a ^ 1;
            float4 xv0 = *reinterpret_cast<const float4*>(xr + j4a * 4);
            float4 xv1 = *reinterpret_cast<const float4*>(xr + j4b * 4);
            float4 av0 = *reinterpret_cast<const float4*>(aXt + j8 * 8);
            float4 av1 = *reinterpret_cast<const float4*>(aXt + j8 * 8 + 4);
            float4 o0, o1;
            TSB_STEP(xv0.x, av0.x, o0.x);
            TSB_STEP(xv0.y, av0.y, o0.y);
            TSB_STEP(xv0.z, av0.z, o0.z);
            TSB_STEP(xv0.w, av0.w, o0.w);
            TSB_STEP(xv1.x, av1.x, o1.x);
            TSB_STEP(xv1.y, av1.y, o1.y);
            TSB_STEP(xv1.z, av1.z, o1.z);
            TSB_STEP(xv1.w, av1.w, o1.w);
            // 32B-aligned pair -> fully-written DRAM sector
            *reinterpret_cast<float4*>(og + j8 * 8)     = o0;
            *reinterpret_cast<float4*>(og + j8 * 8 + 4) = o1;
        }
    }
#undef TSB_STEP
}

extern "C" void kernel_launch(void* const* d_in, const int* in_sizes, int n_in,
                              void* d_out, int out_size) {
    const float* x       = (const float*)d_in[0];   // (B, T, 1) float32
    const float* alpha_p = (const float*)d_in[1];   // (1, 1)
    const float* beta_p  = (const float*)d_in[2];   // (1, 1)
    float* out = (float*)d_out;

    int batch = in_sizes[0] / T_LEN;                // 8192
    int grid  = batch / ROWS;                       // 128 CTAs -> one wave

    cudaFuncSetAttribute(tsb_kernel, cudaFuncAttributeMaxDynamicSharedMemorySize,
                         SMEM_BYTES);
    tsb_kernel<<<grid, THREADS, SMEM_BYTES>>>(x, alpha_p, beta_p, out);
}